// round 14
// baseline (speedup 1.0000x reference)
#include <cuda_runtime.h>

// Problem constants
#define NF 5
#define B_ 8
#define C_ 64
#define HW 16384
#define CHW (C_ * HW)            // 1,048,576
#define FSTRIDE (B_ * C_ * HW)   // 8,388,608 (one frame)
#define KDIM 320                 // NF * C
#define CP 32                    // channel pairs (C/2)

// Scratch (device globals — no allocations allowed)
__device__ float g_origin[B_ * C_ * HW];                 // 33.5 MB
__device__ unsigned long long g_Wpack[CP * KDIM];        // packed W pairs
__device__ float g_coeff[B_ * C_ * 4];                   // coeff_j per (b,c)

// ---------- f32x2 helpers ----------
__device__ __forceinline__ unsigned long long pack2(float lo, float hi) {
    unsigned long long r;
    asm("mov.b64 %0, {%1, %2};" : "=l"(r) : "f"(lo), "f"(hi));
    return r;
}
__device__ __forceinline__ void unpack2(unsigned long long v, float& lo, float& hi) {
    asm("mov.b64 {%0, %1}, %2;" : "=f"(lo), "=f"(hi) : "l"(v));
}
__device__ __forceinline__ void ffma2(unsigned long long& d,
                                      unsigned long long a,
                                      unsigned long long b) {
    asm("fma.rn.f32x2 %0, %1, %2, %0;" : "+l"(d) : "l"(a), "l"(b));
}

// ---------- Kernel 0: pack W into channel-pair layout Wp[cp][k] ----------
__global__ void prep_w_kernel(const float* __restrict__ W) {
    int idx = blockIdx.x * blockDim.x + threadIdx.x;
    if (idx >= CP * KDIM) return;
    int cp = idx / KDIM;
    int k  = idx % KDIM;
    g_Wpack[idx] = pack2(W[(2 * cp) * KDIM + k], W[(2 * cp + 1) * KDIM + k]);
}

// ---------- Kernel 1: origin[b,c,p] = sum_k W[c,k] * x[k,(b,p)] + bias[c] ----------
// One thread per pixel; 64 channels as 32 f32x2 accumulators.
__global__ __launch_bounds__(256, 2)
void origin_kernel(const float* __restrict__ inp, const float* __restrict__ bias) {
    extern __shared__ unsigned long long Wsh[];  // [CP][KDIM], 80 KB
    for (int i = threadIdx.x; i < CP * KDIM; i += 256) Wsh[i] = g_Wpack[i];
    __syncthreads();

    const int b = blockIdx.y;
    const int p = blockIdx.x * 256 + threadIdx.x;
    const float* x0p = inp + b * CHW + p;  // frame 0, channel 0, pixel p

    unsigned long long acc[CP];
#pragma unroll
    for (int i = 0; i < CP; ++i) acc[i] = 0ULL;

    const ulonglong2* wrow = (const ulonglong2*)Wsh;  // [cp][kk] pairs, 16B each

    // k-pair loop with 1-iteration prefetch. Pair q: f=q/32, cc=2*(q%32).
    float x0 = x0p[0];
    float x1 = x0p[HW];
    const float* xn = x0p + 2 * HW;  // points at pair 1
#pragma unroll 1
    for (int kk = 0; kk < 160; ++kk) {
        const float* pf = (kk < 159) ? xn : x0p;  // dummy-safe on last iter
        float nx0 = pf[0];
        float nx1 = pf[HW];
        unsigned long long xx0 = pack2(x0, x0);
        unsigned long long xx1 = pack2(x1, x1);
#pragma unroll
        for (int cp = 0; cp < CP; ++cp) {
            ulonglong2 w2 = wrow[cp * 160 + kk];  // W pairs for k=2kk, 2kk+1
            ffma2(acc[cp], w2.x, xx0);
            ffma2(acc[cp], w2.y, xx1);
        }
        // advance prefetch pointer from pair kk+1 to pair kk+2
        xn += (((kk + 1) & 31) == 31) ? (FSTRIDE - 62 * HW) : (2 * HW);
        x0 = nx0;
        x1 = nx1;
    }

#pragma unroll
    for (int cp = 0; cp < CP; ++cp) {
        float o0, o1;
        unpack2(acc[cp], o0, o1);
        o0 += __ldg(&bias[2 * cp]);
        o1 += __ldg(&bias[2 * cp + 1]);
        g_origin[(b * C_ + 2 * cp) * HW + p]     = o0;
        g_origin[(b * C_ + 2 * cp + 1) * HW + p] = o1;
    }
}

// ---------- Kernel 2: per-(b,c) reductions -> coeff_j = dot_j / max(sqrt(n2_j),1e-12)^2 ----------
__global__ __launch_bounds__(256)
void reduce_kernel(const float* __restrict__ inp) {
    const int c = blockIdx.x;  // 64
    const int b = blockIdx.y;  // 8
    const int tid = threadIdx.x;

    const float4* o4 = (const float4*)(g_origin + (b * C_ + c) * HW);
    const float4* fr0 = (const float4*)(inp + 0 * FSTRIDE + b * CHW + c * HW);
    const float4* fr1 = (const float4*)(inp + 1 * FSTRIDE + b * CHW + c * HW);
    const float4* fr2 = (const float4*)(inp + 2 * FSTRIDE + b * CHW + c * HW);
    const float4* fr3 = (const float4*)(inp + 3 * FSTRIDE + b * CHW + c * HW);
    const float4* fr4 = (const float4*)(inp + 4 * FSTRIDE + b * CHW + c * HW);

    float dot[4] = {0.f, 0.f, 0.f, 0.f};
    float n2[4]  = {0.f, 0.f, 0.f, 0.f};

#pragma unroll 1
    for (int i = tid; i < HW / 4; i += 256) {
        float4 o  = o4[i];
        float4 xl = fr4[i];
        float4 xj;
#define ACCUM(J, PTR)                                            \
        xj = PTR[i];                                             \
        {                                                        \
            float d;                                             \
            d = xl.x - xj.x; dot[J] += o.x * d; n2[J] += d * d;  \
            d = xl.y - xj.y; dot[J] += o.y * d; n2[J] += d * d;  \
            d = xl.z - xj.z; dot[J] += o.z * d; n2[J] += d * d;  \
            d = xl.w - xj.w; dot[J] += o.w * d; n2[J] += d * d;  \
        }
        ACCUM(0, fr0)
        ACCUM(1, fr1)
        ACCUM(2, fr2)
        ACCUM(3, fr3)
#undef ACCUM
    }

    // warp reduce
#pragma unroll
    for (int j = 0; j < 4; ++j) {
#pragma unroll
        for (int off = 16; off > 0; off >>= 1) {
            dot[j] += __shfl_xor_sync(0xffffffffu, dot[j], off);
            n2[j]  += __shfl_xor_sync(0xffffffffu, n2[j], off);
        }
    }
    __shared__ float sdot[8][4];
    __shared__ float sn2[8][4];
    int warp = tid >> 5, lane = tid & 31;
    if (lane == 0) {
#pragma unroll
        for (int j = 0; j < 4; ++j) {
            sdot[warp][j] = dot[j];
            sn2[warp][j]  = n2[j];
        }
    }
    __syncthreads();
    if (tid == 0) {
#pragma unroll
        for (int j = 0; j < 4; ++j) {
            float D = 0.f, N = 0.f;
#pragma unroll
            for (int w = 0; w < 8; ++w) { D += sdot[w][j]; N += sn2[w][j]; }
            float m = fmaxf(sqrtf(N), 1e-12f);
            g_coeff[(b * C_ + c) * 4 + j] = D / (m * m);
        }
    }
}

// ---------- Kernel 3: y[b,p] = sum_{g,c} beta[b,g,c] * inp[g,b,c,p] + out_b ----------
__global__ __launch_bounds__(256)
void final_kernel(const float* __restrict__ inp,
                  const float* __restrict__ ow,   // out_w [1,128]: ow0=ow[0:64], ow1=ow[64:128]
                  const float* __restrict__ obias,
                  float* __restrict__ out) {
    __shared__ float beta[NF * C_];
    const int b = blockIdx.y;
    const int tid = threadIdx.x;

    for (int idx = tid; idx < NF * C_; idx += 256) {
        int g = idx / C_;
        int c = idx % C_;
        const float* cf = &g_coeff[(b * C_ + c) * 4];
        float w0 = __ldg(&ow[c]);
        if (g < 4) {
            beta[idx] = -w0 * __ldg(&cf[g]);
        } else {
            float s = __ldg(&cf[0]) + __ldg(&cf[1]) + __ldg(&cf[2]) + __ldg(&cf[3]);
            beta[idx] = __ldg(&ow[C_ + c]) + w0 * s;
        }
    }
    __syncthreads();

    const int p4 = blockIdx.x * 256 + tid;  // float4 index, 0..4095
    float ob = __ldg(&obias[0]);
    float4 y;
    y.x = ob; y.y = ob; y.z = ob; y.w = ob;

#pragma unroll 1
    for (int g = 0; g < NF; ++g) {
        const float4* xg = (const float4*)(inp + g * FSTRIDE + b * CHW);
#pragma unroll 8
        for (int c = 0; c < C_; ++c) {
            float w = beta[g * C_ + c];
            float4 x = xg[c * (HW / 4) + p4];
            y.x += w * x.x;
            y.y += w * x.y;
            y.z += w * x.z;
            y.w += w * x.w;
        }
    }
    ((float4*)out)[b * (HW / 4) + p4] = y;
}

extern "C" void kernel_launch(void* const* d_in, const int* in_sizes, int n_in,
                              void* d_out, int out_size) {
    const float* inp      = (const float*)d_in[0];  // [5,8,64,128,128]
    const float* origin_w = (const float*)d_in[1];  // [64,320]
    const float* origin_b = (const float*)d_in[2];  // [64]
    const float* out_w    = (const float*)d_in[3];  // [1,128]
    const float* out_b    = (const float*)d_in[4];  // [1]
    float* out = (float*)d_out;                     // [8,1,128,128]

    // 80 KB dynamic shared for the W tile (above the 48 KB default)
    cudaFuncSetAttribute(origin_kernel,
                         cudaFuncAttributeMaxDynamicSharedMemorySize,
                         CP * KDIM * (int)sizeof(unsigned long long));

    prep_w_kernel<<<(CP * KDIM + 255) / 256, 256>>>(origin_w);

    dim3 g1(HW / 256, B_);
    origin_kernel<<<g1, 256, CP * KDIM * sizeof(unsigned long long)>>>(inp, origin_b);

    dim3 g2(C_, B_);
    reduce_kernel<<<g2, 256>>>(inp);

    dim3 g3(HW / 1024, B_);
    final_kernel<<<g3, 256>>>(inp, out_w, out_b, out);
}

// round 15
// speedup vs baseline: 1.2596x; 1.2596x over previous
#include <cuda_runtime.h>

// Problem constants
#define NF 5
#define B_ 8
#define C_ 64
#define HW 16384
#define CHW (C_ * HW)            // 1,048,576
#define FSTRIDE (B_ * C_ * HW)   // 8,388,608 (one frame)
#define KDIM 320                 // NF * C
#define CP 32                    // channel pairs (C/2)

// Scratch (device globals — no allocations allowed)
__device__ unsigned long long g_Wpack[CP * KDIM];        // packed W pairs
__device__ float g_red[B_ * C_ * 4 * 2];                 // [b][c][j][{dot,n2}]

// ---------- f32x2 helpers ----------
__device__ __forceinline__ unsigned long long pack2(float lo, float hi) {
    unsigned long long r;
    asm("mov.b64 %0, {%1, %2};" : "=l"(r) : "f"(lo), "f"(hi));
    return r;
}
__device__ __forceinline__ void unpack2(unsigned long long v, float& lo, float& hi) {
    asm("mov.b64 {%0, %1}, %2;" : "=f"(lo), "=f"(hi) : "l"(v));
}
__device__ __forceinline__ void ffma2(unsigned long long& d,
                                      unsigned long long a,
                                      unsigned long long b) {
    asm("fma.rn.f32x2 %0, %1, %2, %0;" : "+l"(d) : "l"(a), "l"(b));
}

// ---------- init: zero reduction accumulators, preload out with bias ----------
__global__ void init_kernel(const float* __restrict__ obias, float* __restrict__ out) {
    int i = blockIdx.x * 256 + threadIdx.x;            // 0 .. 131071
    out[i] = __ldg(obias);
    if (i < B_ * C_ * 8) g_red[i] = 0.f;
}

// ---------- pack W into channel-pair layout Wp[cp][k] ----------
__global__ void prep_w_kernel(const float* __restrict__ W) {
    int idx = blockIdx.x * blockDim.x + threadIdx.x;
    if (idx >= CP * KDIM) return;
    int cp = idx / KDIM;
    int k  = idx % KDIM;
    g_Wpack[idx] = pack2(W[(2 * cp) * KDIM + k], W[(2 * cp + 1) * KDIM + k]);
}

// ---------- fused: origin GEMM (pass 1) + dot/n2 reductions (pass 2) ----------
// Block = 256 threads = 256 pixels of one batch b. origin never leaves SMEM.
__global__ __launch_bounds__(256, 2)
void fused_kernel(const float* __restrict__ inp, const float* __restrict__ bias) {
    extern __shared__ unsigned long long sh[];  // 80 KB: W tile, later origin tile
    for (int i = threadIdx.x; i < CP * KDIM; i += 256) sh[i] = g_Wpack[i];
    __syncthreads();

    const int b = blockIdx.y;
    const int pbase = blockIdx.x * 256;
    const int p = pbase + threadIdx.x;
    const float* x0p = inp + b * CHW + p;  // frame 0, channel 0, pixel p

    unsigned long long acc[CP];
#pragma unroll
    for (int i = 0; i < CP; ++i) acc[i] = 0ULL;

    const ulonglong2* wrow = (const ulonglong2*)sh;  // [cp][kk] pairs, 16B each

    // ---- pass 1: 320-k GEMM, 64 channels as 32 f32x2 accumulators ----
    float x0 = x0p[0];
    float x1 = x0p[HW];
    const float* xn = x0p + 2 * HW;
#pragma unroll 1
    for (int kk = 0; kk < 160; ++kk) {
        const float* pf = (kk < 159) ? xn : x0p;
        float nx0 = pf[0];
        float nx1 = pf[HW];
        unsigned long long xx0 = pack2(x0, x0);
        unsigned long long xx1 = pack2(x1, x1);
#pragma unroll
        for (int cp = 0; cp < CP; ++cp) {
            ulonglong2 w2 = wrow[cp * 160 + kk];
            ffma2(acc[cp], w2.x, xx0);
            ffma2(acc[cp], w2.y, xx1);
        }
        xn += (((kk + 1) & 31) == 31) ? (FSTRIDE - 62 * HW) : (2 * HW);
        x0 = nx0;
        x1 = nx1;
    }

    __syncthreads();  // everyone done reading W — safe to overwrite smem

    // ---- stash origin (+bias) into smem: osh[cp][256 px] as float2 ----
    float2* osh = (float2*)sh;  // 64 KB of the 80 KB region
#pragma unroll
    for (int cp = 0; cp < CP; ++cp) {
        float o0, o1;
        unpack2(acc[cp], o0, o1);
        o0 += __ldg(&bias[2 * cp]);
        o1 += __ldg(&bias[2 * cp + 1]);
        osh[cp * 256 + threadIdx.x] = make_float2(o0, o1);
    }
    __syncthreads();

    // ---- pass 2: per-(c,j) dot = <origin, last-inp_j>, n2 = ||last-inp_j||^2 ----
    // warp w handles cp in {w, w+8, w+16, w+24}; lanes stride pixels.
    const int warp = threadIdx.x >> 5;
    const int lane = threadIdx.x & 31;

#pragma unroll 1
    for (int cc = 0; cc < 4; ++cc) {
        const int cp = warp + cc * 8;
        const float* pc0 = inp + b * CHW + (2 * cp) * HW + pbase;

        // layout: [0..7] = c0 (j0 dot, j0 n2, j1 dot, ...), [8..15] = c1
        float a2[16];
#pragma unroll
        for (int t = 0; t < 16; ++t) a2[t] = 0.f;

#pragma unroll
        for (int i = 0; i < 8; ++i) {
            const int px = lane + 32 * i;
            const float2 o = osh[cp * 256 + px];
            const float* pp = pc0 + px;
            const float x4a = pp[4 * FSTRIDE];
            const float x4b = pp[4 * FSTRIDE + HW];
#pragma unroll
            for (int j = 0; j < 4; ++j) {
                float da = x4a - pp[j * FSTRIDE];
                float db = x4b - pp[j * FSTRIDE + HW];
                a2[j * 2 + 0]     += o.x * da;
                a2[j * 2 + 1]     += da * da;
                a2[8 + j * 2 + 0] += o.y * db;
                a2[8 + j * 2 + 1] += db * db;
            }
        }

        // warp reduce 16 values to lane 0
#pragma unroll
        for (int t = 0; t < 16; ++t) {
            float v = a2[t];
#pragma unroll
            for (int off = 16; off > 0; off >>= 1)
                v += __shfl_down_sync(0xffffffffu, v, off);
            a2[t] = v;
        }
        if (lane == 0) {
            float* dst = &g_red[(b * C_ + 2 * cp) * 8];  // 16 consecutive floats (c0, c1)
#pragma unroll
            for (int t = 0; t < 16; ++t) atomicAdd(dst + t, a2[t]);
        }
    }
}

// ---------- final: y[b,p] += sum_c beta[b,g,c] * inp[g,b,c,p], frame-split over z ----------
__global__ __launch_bounds__(128)
void final_kernel(const float* __restrict__ inp,
                  const float* __restrict__ ow,   // out_w [1,128]
                  float* __restrict__ out) {
    __shared__ float beta[C_];
    const int b = blockIdx.y;
    const int g = blockIdx.z;
    const int tid = threadIdx.x;

    if (tid < C_) {
        const float* r = &g_red[(b * C_ + tid) * 8];
        float c0, c1, c2, c3;
        {
            float m;
            m = fmaxf(sqrtf(r[1]), 1e-12f); c0 = r[0] / (m * m);
            m = fmaxf(sqrtf(r[3]), 1e-12f); c1 = r[2] / (m * m);
            m = fmaxf(sqrtf(r[5]), 1e-12f); c2 = r[4] / (m * m);
            m = fmaxf(sqrtf(r[7]), 1e-12f); c3 = r[6] / (m * m);
        }
        float w0 = __ldg(&ow[tid]);
        if (g < 4) {
            float cg = (g == 0) ? c0 : (g == 1) ? c1 : (g == 2) ? c2 : c3;
            beta[tid] = -w0 * cg;
        } else {
            beta[tid] = __ldg(&ow[C_ + tid]) + w0 * (c0 + c1 + c2 + c3);
        }
    }
    __syncthreads();

    const int p4 = blockIdx.x * 128 + tid;  // float4 index within batch b
    const float4* xg = (const float4*)(inp + g * FSTRIDE + b * CHW);
    float4 y = make_float4(0.f, 0.f, 0.f, 0.f);

#pragma unroll 8
    for (int c = 0; c < C_; ++c) {
        float w = beta[c];
        float4 x = xg[c * (HW / 4) + p4];
        y.x += w * x.x;
        y.y += w * x.y;
        y.z += w * x.z;
        y.w += w * x.w;
    }

    float* o = out + b * HW + p4 * 4;
    atomicAdd(o + 0, y.x);
    atomicAdd(o + 1, y.y);
    atomicAdd(o + 2, y.z);
    atomicAdd(o + 3, y.w);
}

extern "C" void kernel_launch(void* const* d_in, const int* in_sizes, int n_in,
                              void* d_out, int out_size) {
    const float* inp      = (const float*)d_in[0];  // [5,8,64,128,128]
    const float* origin_w = (const float*)d_in[1];  // [64,320]
    const float* origin_b = (const float*)d_in[2];  // [64]
    const float* out_w    = (const float*)d_in[3];  // [1,128]
    const float* out_b    = (const float*)d_in[4];  // [1]
    float* out = (float*)d_out;                     // [8,1,128,128]

    const int shbytes = CP * KDIM * (int)sizeof(unsigned long long);  // 80 KB
    cudaFuncSetAttribute(fused_kernel,
                         cudaFuncAttributeMaxDynamicSharedMemorySize, shbytes);

    init_kernel<<<(B_ * HW) / 256, 256>>>(out_b, out);
    prep_w_kernel<<<(CP * KDIM + 255) / 256, 256>>>(origin_w);

    dim3 g1(HW / 256, B_);
    fused_kernel<<<g1, 256, shbytes>>>(inp, origin_b);

    dim3 g3(HW / 4 / 128, B_, NF);  // (32, 8, 5) = 1280 blocks
    final_kernel<<<g3, 128>>>(inp, out_w, out);
}

// round 16
// speedup vs baseline: 1.2625x; 1.0023x over previous
#include <cuda_runtime.h>

// Problem constants
#define NF 5
#define B_ 8
#define C_ 64
#define HW 16384
#define CHW (C_ * HW)            // 1,048,576
#define FSTRIDE (B_ * C_ * HW)   // 8,388,608 (one frame)
#define KDIM 320                 // NF * C
#define CP 32                    // channel pairs (C/2)

// Scratch (device globals — no allocations allowed)
__device__ unsigned long long g_Wpack[CP * KDIM];        // packed W pairs
__device__ float g_red[B_ * C_ * 4 * 2];                 // [b][c][j][{dot,n2}]

// ---------- f32x2 helpers ----------
__device__ __forceinline__ unsigned long long pack2(float lo, float hi) {
    unsigned long long r;
    asm("mov.b64 %0, {%1, %2};" : "=l"(r) : "f"(lo), "f"(hi));
    return r;
}
__device__ __forceinline__ void unpack2(unsigned long long v, float& lo, float& hi) {
    asm("mov.b64 {%0, %1}, %2;" : "=f"(lo), "=f"(hi) : "l"(v));
}
__device__ __forceinline__ void ffma2(unsigned long long& d,
                                      unsigned long long a,
                                      unsigned long long b) {
    asm("fma.rn.f32x2 %0, %1, %2, %0;" : "+l"(d) : "l"(a), "l"(b));
}

// ---------- init: zero reduction accumulators, preload out with bias ----------
__global__ void init_kernel(const float* __restrict__ obias, float* __restrict__ out) {
    int i = blockIdx.x * 256 + threadIdx.x;            // 0 .. 131071
    out[i] = __ldg(obias);
    if (i < B_ * C_ * 8) g_red[i] = 0.f;
}

// ---------- pack W into channel-pair layout Wp[cp][k] ----------
__global__ void prep_w_kernel(const float* __restrict__ W) {
    int idx = blockIdx.x * blockDim.x + threadIdx.x;
    if (idx >= CP * KDIM) return;
    int cp = idx / KDIM;
    int k  = idx % KDIM;
    g_Wpack[idx] = pack2(W[(2 * cp) * KDIM + k], W[(2 * cp + 1) * KDIM + k]);
}

// ---------- fused: origin GEMM (pass 1) + dot/n2 reductions (pass 2) ----------
// Block = 256 threads = 256 pixels of one batch b. origin never leaves SMEM.
__global__ __launch_bounds__(256, 2)
void fused_kernel(const float* __restrict__ inp, const float* __restrict__ bias) {
    extern __shared__ unsigned long long sh[];  // 80 KB: W tile, later origin tile
    for (int i = threadIdx.x; i < CP * KDIM; i += 256) sh[i] = g_Wpack[i];
    __syncthreads();

    const int b = blockIdx.y;
    const int pbase = blockIdx.x * 256;
    const int p = pbase + threadIdx.x;
    const float* x0p = inp + b * CHW + p;  // frame 0, channel 0, pixel p

    unsigned long long acc[CP];
#pragma unroll
    for (int i = 0; i < CP; ++i) acc[i] = 0ULL;

    const ulonglong2* wrow = (const ulonglong2*)sh;  // [cp][kk] pairs, 16B each

    // ---- pass 1: 320-k GEMM, 64 channels as 32 f32x2 accumulators ----
    float x0 = x0p[0];
    float x1 = x0p[HW];
    const float* xn = x0p + 2 * HW;
#pragma unroll 1
    for (int kk = 0; kk < 160; ++kk) {
        const float* pf = (kk < 159) ? xn : x0p;
        float nx0 = pf[0];
        float nx1 = pf[HW];
        unsigned long long xx0 = pack2(x0, x0);
        unsigned long long xx1 = pack2(x1, x1);
#pragma unroll
        for (int cp = 0; cp < CP; ++cp) {
            ulonglong2 w2 = wrow[cp * 160 + kk];
            ffma2(acc[cp], w2.x, xx0);
            ffma2(acc[cp], w2.y, xx1);
        }
        xn += (((kk + 1) & 31) == 31) ? (FSTRIDE - 62 * HW) : (2 * HW);
        x0 = nx0;
        x1 = nx1;
    }

    __syncthreads();  // everyone done reading W — safe to overwrite smem

    // ---- stash origin (+bias) into smem: osh[cp][256 px] as float2 ----
    float2* osh = (float2*)sh;  // 64 KB of the 80 KB region
#pragma unroll
    for (int cp = 0; cp < CP; ++cp) {
        float o0, o1;
        unpack2(acc[cp], o0, o1);
        o0 += __ldg(&bias[2 * cp]);
        o1 += __ldg(&bias[2 * cp + 1]);
        osh[cp * 256 + threadIdx.x] = make_float2(o0, o1);
    }
    __syncthreads();

    // ---- pass 2: per-(c,j) dot = <origin, last-inp_j>, n2 = ||last-inp_j||^2 ----
    // warp w handles cp in {w, w+8, w+16, w+24}; lanes stride pixels.
    const int warp = threadIdx.x >> 5;
    const int lane = threadIdx.x & 31;

#pragma unroll 1
    for (int cc = 0; cc < 4; ++cc) {
        const int cp = warp + cc * 8;
        const float* pc0 = inp + b * CHW + (2 * cp) * HW + pbase;

        // layout: [0..7] = c0 (j0 dot, j0 n2, j1 dot, ...), [8..15] = c1
        float a2[16];
#pragma unroll
        for (int t = 0; t < 16; ++t) a2[t] = 0.f;

#pragma unroll
        for (int i = 0; i < 8; ++i) {
            const int px = lane + 32 * i;
            const float2 o = osh[cp * 256 + px];
            const float* pp = pc0 + px;
            const float x4a = pp[4 * FSTRIDE];
            const float x4b = pp[4 * FSTRIDE + HW];
#pragma unroll
            for (int j = 0; j < 4; ++j) {
                float da = x4a - pp[j * FSTRIDE];
                float db = x4b - pp[j * FSTRIDE + HW];
                a2[j * 2 + 0]     += o.x * da;
                a2[j * 2 + 1]     += da * da;
                a2[8 + j * 2 + 0] += o.y * db;
                a2[8 + j * 2 + 1] += db * db;
            }
        }

        // warp reduce 16 values to lane 0
#pragma unroll
        for (int t = 0; t < 16; ++t) {
            float v = a2[t];
#pragma unroll
            for (int off = 16; off > 0; off >>= 1)
                v += __shfl_down_sync(0xffffffffu, v, off);
            a2[t] = v;
        }
        if (lane == 0) {
            float* dst = &g_red[(b * C_ + 2 * cp) * 8];  // 16 consecutive floats (c0, c1)
#pragma unroll
            for (int t = 0; t < 16; ++t) atomicAdd(dst + t, a2[t]);
        }
    }
}

// ---------- final: y[b,p] += sum_c beta[b,g,c] * inp[g,b,c,p], frame-split over z ----------
__global__ __launch_bounds__(128)
void final_kernel(const float* __restrict__ inp,
                  const float* __restrict__ ow,   // out_w [1,128]
                  float* __restrict__ out) {
    __shared__ float beta[C_];
    const int b = blockIdx.y;
    const int g = blockIdx.z;
    const int tid = threadIdx.x;

    if (tid < C_) {
        const float* r = &g_red[(b * C_ + tid) * 8];
        float c0, c1, c2, c3;
        {
            float m;
            m = fmaxf(sqrtf(r[1]), 1e-12f); c0 = r[0] / (m * m);
            m = fmaxf(sqrtf(r[3]), 1e-12f); c1 = r[2] / (m * m);
            m = fmaxf(sqrtf(r[5]), 1e-12f); c2 = r[4] / (m * m);
            m = fmaxf(sqrtf(r[7]), 1e-12f); c3 = r[6] / (m * m);
        }
        float w0 = __ldg(&ow[tid]);
        if (g < 4) {
            float cg = (g == 0) ? c0 : (g == 1) ? c1 : (g == 2) ? c2 : c3;
            beta[tid] = -w0 * cg;
        } else {
            beta[tid] = __ldg(&ow[C_ + tid]) + w0 * (c0 + c1 + c2 + c3);
        }
    }
    __syncthreads();

    const int p4 = blockIdx.x * 128 + tid;  // float4 index within batch b
    const float4* xg = (const float4*)(inp + g * FSTRIDE + b * CHW);
    float4 y = make_float4(0.f, 0.f, 0.f, 0.f);

#pragma unroll 8
    for (int c = 0; c < C_; ++c) {
        float w = beta[c];
        float4 x = xg[c * (HW / 4) + p4];
        y.x += w * x.x;
        y.y += w * x.y;
        y.z += w * x.z;
        y.w += w * x.w;
    }

    float* o = out + b * HW + p4 * 4;
    atomicAdd(o + 0, y.x);
    atomicAdd(o + 1, y.y);
    atomicAdd(o + 2, y.z);
    atomicAdd(o + 3, y.w);
}

extern "C" void kernel_launch(void* const* d_in, const int* in_sizes, int n_in,
                              void* d_out, int out_size) {
    const float* inp      = (const float*)d_in[0];  // [5,8,64,128,128]
    const float* origin_w = (const float*)d_in[1];  // [64,320]
    const float* origin_b = (const float*)d_in[2];  // [64]
    const float* out_w    = (const float*)d_in[3];  // [1,128]
    const float* out_b    = (const float*)d_in[4];  // [1]
    float* out = (float*)d_out;                     // [8,1,128,128]

    const int shbytes = CP * KDIM * (int)sizeof(unsigned long long);  // 80 KB
    cudaFuncSetAttribute(fused_kernel,
                         cudaFuncAttributeMaxDynamicSharedMemorySize, shbytes);

    init_kernel<<<(B_ * HW) / 256, 256>>>(out_b, out);
    prep_w_kernel<<<(CP * KDIM + 255) / 256, 256>>>(origin_w);

    dim3 g1(HW / 256, B_);
    fused_kernel<<<g1, 256, shbytes>>>(inp, origin_b);

    dim3 g3(HW / 4 / 128, B_, NF);  // (32, 8, 5) = 1280 blocks
    final_kernel<<<g3, 128>>>(inp, out_w, out);
}

// round 17
// speedup vs baseline: 1.2627x; 1.0001x over previous
#include <cuda_runtime.h>

// Problem constants
#define NF 5
#define B_ 8
#define C_ 64
#define HW 16384
#define CHW (C_ * HW)            // 1,048,576
#define FSTRIDE (B_ * C_ * HW)   // 8,388,608 (one frame)
#define KDIM 320                 // NF * C
#define CP 32                    // channel pairs (C/2)

// Scratch (device globals — no allocations allowed)
__device__ unsigned long long g_Wpack[CP * KDIM];        // packed W pairs
__device__ float g_red[B_ * C_ * 4 * 2];                 // [b][c][j][{dot,n2}]

// ---------- f32x2 helpers ----------
__device__ __forceinline__ unsigned long long pack2(float lo, float hi) {
    unsigned long long r;
    asm("mov.b64 %0, {%1, %2};" : "=l"(r) : "f"(lo), "f"(hi));
    return r;
}
__device__ __forceinline__ void unpack2(unsigned long long v, float& lo, float& hi) {
    asm("mov.b64 {%0, %1}, %2;" : "=f"(lo), "=f"(hi) : "l"(v));
}
__device__ __forceinline__ void ffma2(unsigned long long& d,
                                      unsigned long long a,
                                      unsigned long long b) {
    asm("fma.rn.f32x2 %0, %1, %2, %0;" : "+l"(d) : "l"(a), "l"(b));
}

// ---------- init: zero reduction accumulators, preload out with bias ----------
__global__ void init_kernel(const float* __restrict__ obias, float* __restrict__ out) {
    int i = blockIdx.x * 256 + threadIdx.x;            // 0 .. 131071
    out[i] = __ldg(obias);
    if (i < B_ * C_ * 8) g_red[i] = 0.f;
}

// ---------- pack W into channel-pair layout Wp[cp][k] ----------
__global__ void prep_w_kernel(const float* __restrict__ W) {
    int idx = blockIdx.x * blockDim.x + threadIdx.x;
    if (idx >= CP * KDIM) return;
    int cp = idx / KDIM;
    int k  = idx % KDIM;
    g_Wpack[idx] = pack2(W[(2 * cp) * KDIM + k], W[(2 * cp + 1) * KDIM + k]);
}

// ---------- fused: origin GEMM (pass 1) + dot/n2 reductions (pass 2) ----------
// Block = 256 threads = 256 pixels of one batch b. origin never leaves SMEM.
__global__ __launch_bounds__(256, 2)
void fused_kernel(const float* __restrict__ inp, const float* __restrict__ bias) {
    extern __shared__ unsigned long long sh[];  // 80 KB: W tile, later origin tile
    for (int i = threadIdx.x; i < CP * KDIM; i += 256) sh[i] = g_Wpack[i];
    __syncthreads();

    const int b = blockIdx.y;
    const int pbase = blockIdx.x * 256;
    const int p = pbase + threadIdx.x;
    const float* x0p = inp + b * CHW + p;  // frame 0, channel 0, pixel p

    unsigned long long acc[CP];
#pragma unroll
    for (int i = 0; i < CP; ++i) acc[i] = 0ULL;

    const ulonglong2* wrow = (const ulonglong2*)sh;  // [cp][kk] pairs, 16B each

    // ---- pass 1: 320-k GEMM, 64 channels as 32 f32x2 accumulators ----
    float x0 = x0p[0];
    float x1 = x0p[HW];
    const float* xn = x0p + 2 * HW;
#pragma unroll 1
    for (int kk = 0; kk < 160; ++kk) {
        const float* pf = (kk < 159) ? xn : x0p;
        float nx0 = pf[0];
        float nx1 = pf[HW];
        unsigned long long xx0 = pack2(x0, x0);
        unsigned long long xx1 = pack2(x1, x1);
#pragma unroll
        for (int cp = 0; cp < CP; ++cp) {
            ulonglong2 w2 = wrow[cp * 160 + kk];
            ffma2(acc[cp], w2.x, xx0);
            ffma2(acc[cp], w2.y, xx1);
        }
        xn += (((kk + 1) & 31) == 31) ? (FSTRIDE - 62 * HW) : (2 * HW);
        x0 = nx0;
        x1 = nx1;
    }

    __syncthreads();  // everyone done reading W — safe to overwrite smem

    // ---- stash origin (+bias) into smem: osh[cp][256 px] as float2 ----
    float2* osh = (float2*)sh;  // 64 KB of the 80 KB region
#pragma unroll
    for (int cp = 0; cp < CP; ++cp) {
        float o0, o1;
        unpack2(acc[cp], o0, o1);
        o0 += __ldg(&bias[2 * cp]);
        o1 += __ldg(&bias[2 * cp + 1]);
        osh[cp * 256 + threadIdx.x] = make_float2(o0, o1);
    }
    __syncthreads();

    // ---- pass 2: per-(c,j) dot = <origin, last-inp_j>, n2 = ||last-inp_j||^2 ----
    // warp w handles cp in {w, w+8, w+16, w+24}; lanes stride pixels.
    const int warp = threadIdx.x >> 5;
    const int lane = threadIdx.x & 31;

#pragma unroll 1
    for (int cc = 0; cc < 4; ++cc) {
        const int cp = warp + cc * 8;
        const float* pc0 = inp + b * CHW + (2 * cp) * HW + pbase;

        // layout: [0..7] = c0 (j0 dot, j0 n2, j1 dot, ...), [8..15] = c1
        float a2[16];
#pragma unroll
        for (int t = 0; t < 16; ++t) a2[t] = 0.f;

#pragma unroll
        for (int i = 0; i < 8; ++i) {
            const int px = lane + 32 * i;
            const float2 o = osh[cp * 256 + px];
            const float* pp = pc0 + px;
            const float x4a = pp[4 * FSTRIDE];
            const float x4b = pp[4 * FSTRIDE + HW];
#pragma unroll
            for (int j = 0; j < 4; ++j) {
                float da = x4a - pp[j * FSTRIDE];
                float db = x4b - pp[j * FSTRIDE + HW];
                a2[j * 2 + 0]     += o.x * da;
                a2[j * 2 + 1]     += da * da;
                a2[8 + j * 2 + 0] += o.y * db;
                a2[8 + j * 2 + 1] += db * db;
            }
        }

        // warp reduce 16 values to lane 0
#pragma unroll
        for (int t = 0; t < 16; ++t) {
            float v = a2[t];
#pragma unroll
            for (int off = 16; off > 0; off >>= 1)
                v += __shfl_down_sync(0xffffffffu, v, off);
            a2[t] = v;
        }
        if (lane == 0) {
            float* dst = &g_red[(b * C_ + 2 * cp) * 8];  // 16 consecutive floats (c0, c1)
#pragma unroll
            for (int t = 0; t < 16; ++t) atomicAdd(dst + t, a2[t]);
        }
    }
}

// ---------- final: y[b,p] += sum_c beta[b,g,c] * inp[g,b,c,p], frame-split over z ----------
__global__ __launch_bounds__(128)
void final_kernel(const float* __restrict__ inp,
                  const float* __restrict__ ow,   // out_w [1,128]
                  float* __restrict__ out) {
    __shared__ float beta[C_];
    const int b = blockIdx.y;
    const int g = blockIdx.z;
    const int tid = threadIdx.x;

    if (tid < C_) {
        const float* r = &g_red[(b * C_ + tid) * 8];
        float c0, c1, c2, c3;
        {
            float m;
            m = fmaxf(sqrtf(r[1]), 1e-12f); c0 = r[0] / (m * m);
            m = fmaxf(sqrtf(r[3]), 1e-12f); c1 = r[2] / (m * m);
            m = fmaxf(sqrtf(r[5]), 1e-12f); c2 = r[4] / (m * m);
            m = fmaxf(sqrtf(r[7]), 1e-12f); c3 = r[6] / (m * m);
        }
        float w0 = __ldg(&ow[tid]);
        if (g < 4) {
            float cg = (g == 0) ? c0 : (g == 1) ? c1 : (g == 2) ? c2 : c3;
            beta[tid] = -w0 * cg;
        } else {
            beta[tid] = __ldg(&ow[C_ + tid]) + w0 * (c0 + c1 + c2 + c3);
        }
    }
    __syncthreads();

    const int p4 = blockIdx.x * 128 + tid;  // float4 index within batch b
    const float4* xg = (const float4*)(inp + g * FSTRIDE + b * CHW);
    float4 y = make_float4(0.f, 0.f, 0.f, 0.f);

#pragma unroll 8
    for (int c = 0; c < C_; ++c) {
        float w = beta[c];
        float4 x = xg[c * (HW / 4) + p4];
        y.x += w * x.x;
        y.y += w * x.y;
        y.z += w * x.z;
        y.w += w * x.w;
    }

    float* o = out + b * HW + p4 * 4;
    atomicAdd(o + 0, y.x);
    atomicAdd(o + 1, y.y);
    atomicAdd(o + 2, y.z);
    atomicAdd(o + 3, y.w);
}

extern "C" void kernel_launch(void* const* d_in, const int* in_sizes, int n_in,
                              void* d_out, int out_size) {
    const float* inp      = (const float*)d_in[0];  // [5,8,64,128,128]
    const float* origin_w = (const float*)d_in[1];  // [64,320]
    const float* origin_b = (const float*)d_in[2];  // [64]
    const float* out_w    = (const float*)d_in[3];  // [1,128]
    const float* out_b    = (const float*)d_in[4];  // [1]
    float* out = (float*)d_out;                     // [8,1,128,128]

    const int shbytes = CP * KDIM * (int)sizeof(unsigned long long);  // 80 KB
    cudaFuncSetAttribute(fused_kernel,
                         cudaFuncAttributeMaxDynamicSharedMemorySize, shbytes);

    init_kernel<<<(B_ * HW) / 256, 256>>>(out_b, out);
    prep_w_kernel<<<(CP * KDIM + 255) / 256, 256>>>(origin_w);

    dim3 g1(HW / 256, B_);
    fused_kernel<<<g1, 256, shbytes>>>(inp, origin_b);

    dim3 g3(HW / 4 / 128, B_, NF);  // (32, 8, 5) = 1280 blocks
    final_kernel<<<g3, 128>>>(inp, out_w, out);
}